// round 6
// baseline (speedup 1.0000x reference)
#include <cuda_runtime.h>

// ---------------- static scratch (no allocations allowed) ----------------
#define MAXN0 600000
__device__ float g_x0[MAXN0 * 16];
__device__ float g_x1[MAXN0 * 16];
__device__ float g_x2[MAXN0 * 32];
__device__ float g_r0[MAXN0 * 32];
__device__ float g_r1[MAXN0 * 32];
__device__ int   g_gi0[27 * MAXN0];
__device__ int   g_gid[8 * MAXN0];
__device__ int   g_gi1[27 * MAXN0];

typedef unsigned long long u64;
union F2U { u64 u; float2 f; };

__device__ __forceinline__ u64 bcast2(float s) {
    u64 r; asm("mov.b64 %0, {%1, %1};" : "=l"(r) : "r"(__float_as_uint(s))); return r;
}
__device__ __forceinline__ void ffma2(u64& a, u64 x, u64 w) {
    asm("fma.rn.f32x2 %0, %1, %2, %3;" : "=l"(a) : "l"(x), "l"(w), "l"(a));
}
__device__ __forceinline__ u64 packf2(float lo, float hi) {
    u64 r; asm("mov.b64 %0, {%1, %2};" : "=l"(r) : "r"(__float_as_uint(lo)), "r"(__float_as_uint(hi))); return r;
}

// ---------------- inverse-map build ----------------
__global__ void build_gi(const int* __restrict__ kin, const int* __restrict__ kout,
                         int* __restrict__ gi, int P, int n) {
    const int k = blockIdx.y;
    int p = blockIdx.x * blockDim.x + threadIdx.x;
    if (p >= P) return;
    const size_t base = (size_t)k * P;
    int j = kout[base + p];
    if (j < n) gi[(size_t)k * n + j] = kin[base + p];
}

// ---------------- conv 1->16: one thread per output row -----------------
__global__ __launch_bounds__(256) void conv1_16(const float* __restrict__ x,
        const float* __restrict__ W, const int* __restrict__ gi,
        const float* __restrict__ b, float* __restrict__ out,
        float* __restrict__ cache, int n) {
    __shared__ float Ws[27 * 16];
    for (int t = threadIdx.x; t < 27 * 16; t += 256) Ws[t] = W[t];
    __syncthreads();
    int j = blockIdx.x * 256 + threadIdx.x;
    if (j >= n) return;
    float acc[16];
#pragma unroll
    for (int c = 0; c < 16; ++c) acc[c] = __ldg(b + c);
#pragma unroll
    for (int k = 0; k < 27; ++k) {
        int i = __ldg(gi + (size_t)k * n + j);
        if (i >= 0) {
            float xv = __ldg(x + i);
#pragma unroll
            for (int c = 0; c < 16; ++c) acc[c] += xv * Ws[k * 16 + c];
        }
    }
    float4* o4 = (float4*)(out + (size_t)j * 16);
    float4* c4 = (float4*)(cache + (size_t)j * 16);
#pragma unroll
    for (int r = 0; r < 4; ++r) {
        float4 v = make_float4(fmaxf(acc[4*r], 0.f), fmaxf(acc[4*r+1], 0.f),
                               fmaxf(acc[4*r+2], 0.f), fmaxf(acc[4*r+3], 0.f));
        o4[r] = v; c4[r] = v;
    }
}

// ---------------- conv 16->16 (K=27): lane owns output row --------------
// Per k: 256 floats = 64 ulonglong2. Row cc = 16 floats = 4 ulonglong2.
__global__ __launch_bounds__(256, 4) void conv16_16(const float* __restrict__ x,
        const float* __restrict__ W, const int* __restrict__ gi,
        const float* __restrict__ b, float* __restrict__ out, int n) {
    __shared__ float4 Ws4[27 * 64];          // 27 KB
    const float4* Wg = (const float4*)W;
    for (int t = threadIdx.x; t < 27 * 64; t += 256) Ws4[t] = Wg[t];
    __syncthreads();
    const ulonglong2* Wu = (const ulonglong2*)Ws4;
    int j = blockIdx.x * 256 + threadIdx.x;
    bool jv = j < n;
    u64 acc[8];
    {
        const float4* b4 = (const float4*)b;
#pragma unroll
        for (int r = 0; r < 4; ++r) {
            float4 bb = __ldg(b4 + r);
            acc[2*r] = packf2(bb.x, bb.y); acc[2*r+1] = packf2(bb.z, bb.w);
        }
    }
    int inext = jv ? __ldg(gi + j) : -1;
    for (int k = 0; k < 27; ++k) {
        int i = inext;
        inext = (k < 26 && jv) ? __ldg(gi + (size_t)(k + 1) * n + j) : -1;
        if (!__ballot_sync(0xffffffffu, i >= 0)) continue;
        float4 X[4];
        const float4* xr = (const float4*)(x + (size_t)(i < 0 ? 0 : i) * 16);
#pragma unroll
        for (int q = 0; q < 4; ++q)
            X[q] = (i >= 0) ? __ldg(xr + q) : make_float4(0.f, 0.f, 0.f, 0.f);
        const ulonglong2* Wk = Wu + (size_t)k * 64;
#pragma unroll
        for (int q = 0; q < 4; ++q) {
            float xs[4] = {X[q].x, X[q].y, X[q].z, X[q].w};
#pragma unroll
            for (int s = 0; s < 4; ++s) {
                int cc = q * 4 + s;
                u64 xx = bcast2(xs[s]);
#pragma unroll
                for (int r = 0; r < 4; ++r) {
                    ulonglong2 wp = Wk[cc * 4 + r];
                    ffma2(acc[2*r],     xx, wp.x);
                    ffma2(acc[2*r + 1], xx, wp.y);
                }
            }
        }
    }
    if (jv) {
        float4* o4 = (float4*)(out + (size_t)j * 16);
#pragma unroll
        for (int r = 0; r < 4; ++r) {
            F2U a0, a1; a0.u = acc[2*r]; a1.u = acc[2*r+1];
            o4[r] = make_float4(fmaxf(a0.f.x, 0.f), fmaxf(a0.f.y, 0.f),
                                fmaxf(a1.f.x, 0.f), fmaxf(a1.f.y, 0.f));
        }
    }
}

// ---------------- conv 16->32 (K=8, downsample) -------------------------
// Per k: 512 floats = 128 ulonglong2. Row cc = 32 floats = 8 ulonglong2.
__global__ __launch_bounds__(512, 2) void conv16_32(const float* __restrict__ x,
        const float* __restrict__ W, const int* __restrict__ gi,
        const float* __restrict__ b, float* __restrict__ out, int n) {
    __shared__ float4 Ws4[8 * 128];          // 16 KB
    const float4* Wg = (const float4*)W;
    for (int t = threadIdx.x; t < 8 * 128; t += 512) Ws4[t] = Wg[t];
    __syncthreads();
    const ulonglong2* Wu = (const ulonglong2*)Ws4;
    int j = blockIdx.x * 512 + threadIdx.x;
    bool jv = j < n;
    u64 acc[16];
    {
        const float4* b4 = (const float4*)b;
#pragma unroll
        for (int r = 0; r < 8; ++r) {
            float4 bb = __ldg(b4 + r);
            acc[2*r] = packf2(bb.x, bb.y); acc[2*r+1] = packf2(bb.z, bb.w);
        }
    }
    int inext = jv ? __ldg(gi + j) : -1;
    for (int k = 0; k < 8; ++k) {
        int i = inext;
        inext = (k < 7 && jv) ? __ldg(gi + (size_t)(k + 1) * n + j) : -1;
        if (!__ballot_sync(0xffffffffu, i >= 0)) continue;
        float4 X[4];
        const float4* xr = (const float4*)(x + (size_t)(i < 0 ? 0 : i) * 16);
#pragma unroll
        for (int q = 0; q < 4; ++q)
            X[q] = (i >= 0) ? __ldg(xr + q) : make_float4(0.f, 0.f, 0.f, 0.f);
        const ulonglong2* Wk = Wu + (size_t)k * 128;
#pragma unroll
        for (int q = 0; q < 4; ++q) {
            float xs[4] = {X[q].x, X[q].y, X[q].z, X[q].w};
#pragma unroll
            for (int s = 0; s < 4; ++s) {
                int cc = q * 4 + s;
                u64 xx = bcast2(xs[s]);
#pragma unroll
                for (int r = 0; r < 8; ++r) {
                    ulonglong2 wp = Wk[cc * 8 + r];
                    ffma2(acc[2*r],     xx, wp.x);
                    ffma2(acc[2*r + 1], xx, wp.y);
                }
            }
        }
    }
    if (jv) {
        float4* o4 = (float4*)(out + (size_t)j * 32);
#pragma unroll
        for (int r = 0; r < 8; ++r) {
            F2U a0, a1; a0.u = acc[2*r]; a1.u = acc[2*r+1];
            o4[r] = make_float4(fmaxf(a0.f.x, 0.f), fmaxf(a0.f.y, 0.f),
                                fmaxf(a1.f.x, 0.f), fmaxf(a1.f.y, 0.f));
        }
    }
}

// ---------------- conv 32->32 (K=27): lane owns output row --------------
// Per k: 1024 floats = 256 ulonglong2 (<-- the R4/R5 bug was k*128).
// Row cc = 32 floats = 8 ulonglong2.
template <int EPI>   // 0 = bias+relu, 1 = bias+residual, 2 = bias only
__global__ __launch_bounds__(512, 2) void conv32_32(const float* __restrict__ x,
        const float* __restrict__ W, const int* __restrict__ gi,
        const float* __restrict__ b, const float* __restrict__ skip,
        float* __restrict__ out, int n) {
    extern __shared__ float4 Ws4[];          // 27 * 256 float4 = 108 KB
    const float4* Wg = (const float4*)W;
    for (int t = threadIdx.x; t < 27 * 256; t += 512) Ws4[t] = Wg[t];
    __syncthreads();
    const ulonglong2* Wu = (const ulonglong2*)Ws4;
    int j = blockIdx.x * 512 + threadIdx.x;
    bool jv = j < n;
    u64 acc[16];
    {
        const float4* b4 = (const float4*)b;
#pragma unroll
        for (int r = 0; r < 8; ++r) {
            float4 bb = __ldg(b4 + r);
            acc[2*r] = packf2(bb.x, bb.y); acc[2*r+1] = packf2(bb.z, bb.w);
        }
    }
    int inext = jv ? __ldg(gi + j) : -1;
    for (int k = 0; k < 27; ++k) {
        int i = inext;
        inext = (k < 26 && jv) ? __ldg(gi + (size_t)(k + 1) * n + j) : -1;
        if (!__ballot_sync(0xffffffffu, i >= 0)) continue;
        const float4* xr = (const float4*)(x + (size_t)(i < 0 ? 0 : i) * 32);
        const ulonglong2* Wk = Wu + (size_t)k * 256;
#pragma unroll
        for (int h = 0; h < 2; ++h) {        // two input-channel halves keep regs low
            float4 X[4];
#pragma unroll
            for (int q = 0; q < 4; ++q)
                X[q] = (i >= 0) ? __ldg(xr + h * 4 + q) : make_float4(0.f, 0.f, 0.f, 0.f);
#pragma unroll
            for (int q = 0; q < 4; ++q) {
                float xs[4] = {X[q].x, X[q].y, X[q].z, X[q].w};
#pragma unroll
                for (int s = 0; s < 4; ++s) {
                    int cc = h * 16 + q * 4 + s;
                    u64 xx = bcast2(xs[s]);
#pragma unroll
                    for (int r = 0; r < 8; ++r) {
                        ulonglong2 wp = Wk[cc * 8 + r];
                        ffma2(acc[2*r],     xx, wp.x);
                        ffma2(acc[2*r + 1], xx, wp.y);
                    }
                }
            }
        }
    }
    if (jv) {
        float4* o4 = (float4*)(out + (size_t)j * 32);
        const float4* s4 = (EPI == 1) ? (const float4*)(skip + (size_t)j * 32) : nullptr;
#pragma unroll
        for (int r = 0; r < 8; ++r) {
            F2U a0, a1; a0.u = acc[2*r]; a1.u = acc[2*r+1];
            float4 v = make_float4(a0.f.x, a0.f.y, a1.f.x, a1.f.y);
            if (EPI == 0) {
                v.x = fmaxf(v.x, 0.f); v.y = fmaxf(v.y, 0.f);
                v.z = fmaxf(v.z, 0.f); v.w = fmaxf(v.w, 0.f);
            }
            if (EPI == 1) {
                float4 sv = __ldg(s4 + r);
                v.x += sv.x; v.y += sv.y; v.z += sv.z; v.w += sv.w;
            }
            o4[r] = v;
        }
    }
}

// ---------------- host orchestration ----------------
extern "C" void kernel_launch(void* const* d_in, const int* in_sizes, int n_in,
                              void* d_out, int out_size) {
    const float* in_feats = (const float*)d_in[0];
    const float* W_first  = (const float*)d_in[1];
    const float* b_first  = (const float*)d_in[2];
    const float* W_pre    = (const float*)d_in[3];
    const float* b_pre    = (const float*)d_in[4];
    const float* W_down   = (const float*)d_in[5];
    const float* b_down   = (const float*)d_in[6];
    const float* W_r0     = (const float*)d_in[7];
    const float* b_r0     = (const float*)d_in[8];
    const float* W_r1     = (const float*)d_in[9];
    const float* b_r1     = (const float*)d_in[10];
    const float* W_fin    = (const float*)d_in[11];
    const float* b_fin    = (const float*)d_in[12];
    const int* km0_in  = (const int*)d_in[13];
    const int* km0_out = (const int*)d_in[14];
    const int* kmd_in  = (const int*)d_in[15];
    const int* kmd_out = (const int*)d_in[16];
    const int* km1_in  = (const int*)d_in[17];
    const int* km1_out = (const int*)d_in[18];

    const int n0 = in_sizes[0];
    const int P0 = in_sizes[13] / 27;
    const int Pd = in_sizes[15] / 8;
    const int P1 = in_sizes[17] / 27;
    const int n1 = (out_size - n0 * 16) / 32;

    float* out_fin    = (float*)d_out;
    float* out_cached = (float*)d_out + (size_t)n1 * 32;

    float *x0, *x1, *x2, *r0, *r1;
    int *gi0, *gid, *gi1;
    cudaGetSymbolAddress((void**)&x0, g_x0);
    cudaGetSymbolAddress((void**)&x1, g_x1);
    cudaGetSymbolAddress((void**)&x2, g_x2);
    cudaGetSymbolAddress((void**)&r0, g_r0);
    cudaGetSymbolAddress((void**)&r1, g_r1);
    cudaGetSymbolAddress((void**)&gi0, g_gi0);
    cudaGetSymbolAddress((void**)&gid, g_gid);
    cudaGetSymbolAddress((void**)&gi1, g_gi1);

    const int SMEM32 = 27 * 256 * sizeof(float4);  // 110592 B
    static bool attr_done = false;
    if (!attr_done) {
        cudaFuncSetAttribute(conv32_32<0>, cudaFuncAttributeMaxDynamicSharedMemorySize, SMEM32);
        cudaFuncSetAttribute(conv32_32<1>, cudaFuncAttributeMaxDynamicSharedMemorySize, SMEM32);
        cudaFuncSetAttribute(conv32_32<2>, cudaFuncAttributeMaxDynamicSharedMemorySize, SMEM32);
        attr_done = true;
    }

    auto ceil_div = [](int a, int b) { return (a + b - 1) / b; };
    const int T = 256;

    // ---- build inverse maps ----
    cudaMemsetAsync(gi0, 0xFF, (size_t)27 * n0 * sizeof(int), 0);
    cudaMemsetAsync(gid, 0xFF, (size_t)8 * n1 * sizeof(int), 0);
    cudaMemsetAsync(gi1, 0xFF, (size_t)27 * n1 * sizeof(int), 0);
    {
        dim3 g0(ceil_div(P0, T), 27);
        build_gi<<<g0, T>>>(km0_in, km0_out, gi0, P0, n0);
        dim3 gd(ceil_div(Pd, T), 8);
        build_gi<<<gd, T>>>(kmd_in, kmd_out, gid, Pd, n1);
        dim3 g1(ceil_div(P1, T), 27);
        build_gi<<<g1, T>>>(km1_in, km1_out, gi1, P1, n1);
    }

    conv1_16<<<ceil_div(n0, T), T>>>(in_feats, W_first, gi0, b_first, x0, out_cached, n0);
    conv16_16<<<ceil_div(n0, T), T>>>(x0, W_pre, gi0, b_pre, x1, n0);
    conv16_32<<<ceil_div(n1, 512), 512>>>(x1, W_down, gid, b_down, x2, n1);
    conv32_32<0><<<ceil_div(n1, 512), 512, SMEM32>>>(x2, W_r0, gi1, b_r0, nullptr, r0, n1);
    conv32_32<1><<<ceil_div(n1, 512), 512, SMEM32>>>(r0, W_r1, gi1, b_r1, x2, r1, n1);
    conv32_32<2><<<ceil_div(n1, 512), 512, SMEM32>>>(r1, W_fin, gi1, b_fin, nullptr, out_fin, n1);
}

// round 7
// speedup vs baseline: 1.0056x; 1.0056x over previous
#include <cuda_runtime.h>

// ---------------- static scratch (no allocations allowed) ----------------
#define MAXN0 600000
__device__ float g_x0[MAXN0 * 16];
__device__ float g_x1[MAXN0 * 16];
__device__ float g_x2[MAXN0 * 32];
__device__ float g_r0[MAXN0 * 32];
__device__ float g_r1[MAXN0 * 32];
__device__ int   g_gi0[27 * MAXN0];
__device__ int   g_gid[8 * MAXN0];
__device__ int   g_gi1[27 * MAXN0];

typedef unsigned long long u64;
union F2U { u64 u; float2 f; };

__device__ __forceinline__ u64 bcast2(float s) {
    u64 r; asm("mov.b64 %0, {%1, %1};" : "=l"(r) : "r"(__float_as_uint(s))); return r;
}
__device__ __forceinline__ void ffma2(u64& a, u64 x, u64 w) {
    asm("fma.rn.f32x2 %0, %1, %2, %3;" : "=l"(a) : "l"(x), "l"(w), "l"(a));
}
__device__ __forceinline__ u64 packf2(float lo, float hi) {
    u64 r; asm("mov.b64 %0, {%1, %2};" : "=l"(r) : "r"(__float_as_uint(lo)), "r"(__float_as_uint(hi))); return r;
}

__device__ __forceinline__ void loadX4(float4* X, const float* x, int i, int rowf) {
    const float4* xr = (const float4*)(x + (size_t)(i < 0 ? 0 : i) * rowf);
#pragma unroll
    for (int q = 0; q < 4; ++q)
        X[q] = (i >= 0) ? __ldg(xr + q) : make_float4(0.f, 0.f, 0.f, 0.f);
}
__device__ __forceinline__ void loadX8(float4* X, const float* x, int i) {
    const float4* xr = (const float4*)(x + (size_t)(i < 0 ? 0 : i) * 32);
#pragma unroll
    for (int q = 0; q < 8; ++q)
        X[q] = (i >= 0) ? __ldg(xr + q) : make_float4(0.f, 0.f, 0.f, 0.f);
}

// ---------------- inverse-map build ----------------
__global__ void build_gi(const int* __restrict__ kin, const int* __restrict__ kout,
                         int* __restrict__ gi, int P, int n) {
    const int k = blockIdx.y;
    int p = blockIdx.x * blockDim.x + threadIdx.x;
    if (p >= P) return;
    const size_t base = (size_t)k * P;
    int j = kout[base + p];
    if (j < n) gi[(size_t)k * n + j] = kin[base + p];
}

// ---------------- conv 1->16: batched-MLP gather ------------------------
__global__ __launch_bounds__(256) void conv1_16(const float* __restrict__ x,
        const float* __restrict__ W, const int* __restrict__ gi,
        const float* __restrict__ b, float* __restrict__ out,
        float* __restrict__ cache, int n) {
    __shared__ float Ws[27 * 16];
    for (int t = threadIdx.x; t < 27 * 16; t += 256) Ws[t] = W[t];
    __syncthreads();
    int j = blockIdx.x * 256 + threadIdx.x;
    if (j >= n) return;
    float acc[16];
#pragma unroll
    for (int c = 0; c < 16; ++c) acc[c] = __ldg(b + c);
#pragma unroll
    for (int kb = 0; kb < 27; kb += 9) {      // batches of 9: MLP=9 on gi then x
        int idx[9];
#pragma unroll
        for (int t = 0; t < 9; ++t) idx[t] = __ldg(gi + (size_t)(kb + t) * n + j);
        float xv[9];
#pragma unroll
        for (int t = 0; t < 9; ++t) xv[t] = (idx[t] >= 0) ? __ldg(x + idx[t]) : 0.f;
#pragma unroll
        for (int t = 0; t < 9; ++t) {
#pragma unroll
            for (int c = 0; c < 16; ++c) acc[c] += xv[t] * Ws[(kb + t) * 16 + c];
        }
    }
    float4* o4 = (float4*)(out + (size_t)j * 16);
    float4* c4 = (float4*)(cache + (size_t)j * 16);
#pragma unroll
    for (int r = 0; r < 4; ++r) {
        float4 v = make_float4(fmaxf(acc[4*r], 0.f), fmaxf(acc[4*r+1], 0.f),
                               fmaxf(acc[4*r+2], 0.f), fmaxf(acc[4*r+3], 0.f));
        o4[r] = v; c4[r] = v;
    }
}

// ---------------- conv 16->16 (K=27): pipelined gather ------------------
__global__ __launch_bounds__(256, 4) void conv16_16(const float* __restrict__ x,
        const float* __restrict__ W, const int* __restrict__ gi,
        const float* __restrict__ b, float* __restrict__ out, int n) {
    __shared__ float4 Ws4[27 * 64];          // 27 KB
    const float4* Wg = (const float4*)W;
    for (int t = threadIdx.x; t < 27 * 64; t += 256) Ws4[t] = Wg[t];
    __syncthreads();
    const ulonglong2* Wu = (const ulonglong2*)Ws4;
    int j = blockIdx.x * 256 + threadIdx.x;
    bool jv = j < n;
    u64 acc[8];
    {
        const float4* b4 = (const float4*)b;
#pragma unroll
        for (int r = 0; r < 4; ++r) {
            float4 bb = __ldg(b4 + r);
            acc[2*r] = packf2(bb.x, bb.y); acc[2*r+1] = packf2(bb.z, bb.w);
        }
    }
    int icur = jv ? __ldg(gi + j) : -1;
    float4 Xn[4];
    loadX4(Xn, x, icur, 16);
    for (int k = 0; k < 27; ++k) {
        float4 Xc[4];
#pragma unroll
        for (int q = 0; q < 4; ++q) Xc[q] = Xn[q];
        int iprev = icur;
        icur = (k < 26 && jv) ? __ldg(gi + (size_t)(k + 1) * n + j) : -1;
        loadX4(Xn, x, icur, 16);             // issue k+1's gather before compute(k)
        if (!__ballot_sync(0xffffffffu, iprev >= 0)) continue;
        const ulonglong2* Wk = Wu + (size_t)k * 64;
#pragma unroll
        for (int q = 0; q < 4; ++q) {
            float xs[4] = {Xc[q].x, Xc[q].y, Xc[q].z, Xc[q].w};
#pragma unroll
            for (int s = 0; s < 4; ++s) {
                int cc = q * 4 + s;
                u64 xx = bcast2(xs[s]);
#pragma unroll
                for (int r = 0; r < 4; ++r) {
                    ulonglong2 wp = Wk[cc * 4 + r];
                    ffma2(acc[2*r],     xx, wp.x);
                    ffma2(acc[2*r + 1], xx, wp.y);
                }
            }
        }
    }
    if (jv) {
        float4* o4 = (float4*)(out + (size_t)j * 16);
#pragma unroll
        for (int r = 0; r < 4; ++r) {
            F2U a0, a1; a0.u = acc[2*r]; a1.u = acc[2*r+1];
            o4[r] = make_float4(fmaxf(a0.f.x, 0.f), fmaxf(a0.f.y, 0.f),
                                fmaxf(a1.f.x, 0.f), fmaxf(a1.f.y, 0.f));
        }
    }
}

// ---------------- conv 16->32 (K=8, downsample): pipelined --------------
__global__ __launch_bounds__(256, 3) void conv16_32(const float* __restrict__ x,
        const float* __restrict__ W, const int* __restrict__ gi,
        const float* __restrict__ b, float* __restrict__ out, int n) {
    __shared__ float4 Ws4[8 * 128];          // 16 KB
    const float4* Wg = (const float4*)W;
    for (int t = threadIdx.x; t < 8 * 128; t += 256) Ws4[t] = Wg[t];
    __syncthreads();
    const ulonglong2* Wu = (const ulonglong2*)Ws4;
    int j = blockIdx.x * 256 + threadIdx.x;
    bool jv = j < n;
    u64 acc[16];
    {
        const float4* b4 = (const float4*)b;
#pragma unroll
        for (int r = 0; r < 8; ++r) {
            float4 bb = __ldg(b4 + r);
            acc[2*r] = packf2(bb.x, bb.y); acc[2*r+1] = packf2(bb.z, bb.w);
        }
    }
    int icur = jv ? __ldg(gi + j) : -1;
    float4 Xn[4];
    loadX4(Xn, x, icur, 16);
    for (int k = 0; k < 8; ++k) {
        float4 Xc[4];
#pragma unroll
        for (int q = 0; q < 4; ++q) Xc[q] = Xn[q];
        int iprev = icur;
        icur = (k < 7 && jv) ? __ldg(gi + (size_t)(k + 1) * n + j) : -1;
        loadX4(Xn, x, icur, 16);
        if (!__ballot_sync(0xffffffffu, iprev >= 0)) continue;
        const ulonglong2* Wk = Wu + (size_t)k * 128;
#pragma unroll
        for (int q = 0; q < 4; ++q) {
            float xs[4] = {Xc[q].x, Xc[q].y, Xc[q].z, Xc[q].w};
#pragma unroll
            for (int s = 0; s < 4; ++s) {
                int cc = q * 4 + s;
                u64 xx = bcast2(xs[s]);
#pragma unroll
                for (int r = 0; r < 8; ++r) {
                    ulonglong2 wp = Wk[cc * 8 + r];
                    ffma2(acc[2*r],     xx, wp.x);
                    ffma2(acc[2*r + 1], xx, wp.y);
                }
            }
        }
    }
    if (jv) {
        float4* o4 = (float4*)(out + (size_t)j * 32);
#pragma unroll
        for (int r = 0; r < 8; ++r) {
            F2U a0, a1; a0.u = acc[2*r]; a1.u = acc[2*r+1];
            o4[r] = make_float4(fmaxf(a0.f.x, 0.f), fmaxf(a0.f.y, 0.f),
                                fmaxf(a1.f.x, 0.f), fmaxf(a1.f.y, 0.f));
        }
    }
}

// ---------------- conv 32->32 (K=27): pipelined gather ------------------
// Per k: 1024 floats = 256 ulonglong2. Row cc = 32 floats = 8 ulonglong2.
template <int EPI>   // 0 = bias+relu, 1 = bias+residual, 2 = bias only
__global__ __launch_bounds__(256, 2) void conv32_32(const float* __restrict__ x,
        const float* __restrict__ W, const int* __restrict__ gi,
        const float* __restrict__ b, const float* __restrict__ skip,
        float* __restrict__ out, int n) {
    extern __shared__ float4 Ws4[];          // 27 * 256 float4 = 108 KB
    const float4* Wg = (const float4*)W;
    for (int t = threadIdx.x; t < 27 * 256; t += 256) Ws4[t] = Wg[t];
    __syncthreads();
    const ulonglong2* Wu = (const ulonglong2*)Ws4;
    int j = blockIdx.x * 256 + threadIdx.x;
    bool jv = j < n;
    u64 acc[16];
    {
        const float4* b4 = (const float4*)b;
#pragma unroll
        for (int r = 0; r < 8; ++r) {
            float4 bb = __ldg(b4 + r);
            acc[2*r] = packf2(bb.x, bb.y); acc[2*r+1] = packf2(bb.z, bb.w);
        }
    }
    int icur = jv ? __ldg(gi + j) : -1;
    float4 Xn[8];
    loadX8(Xn, x, icur);
    for (int k = 0; k < 27; ++k) {
        float4 Xc[8];
#pragma unroll
        for (int q = 0; q < 8; ++q) Xc[q] = Xn[q];
        int iprev = icur;
        icur = (k < 26 && jv) ? __ldg(gi + (size_t)(k + 1) * n + j) : -1;
        loadX8(Xn, x, icur);                 // issue k+1's gather before compute(k)
        if (!__ballot_sync(0xffffffffu, iprev >= 0)) continue;
        const ulonglong2* Wk = Wu + (size_t)k * 256;
#pragma unroll
        for (int q = 0; q < 8; ++q) {
            float xs[4] = {Xc[q].x, Xc[q].y, Xc[q].z, Xc[q].w};
#pragma unroll
            for (int s = 0; s < 4; ++s) {
                int cc = q * 4 + s;
                u64 xx = bcast2(xs[s]);
#pragma unroll
                for (int r = 0; r < 8; ++r) {
                    ulonglong2 wp = Wk[cc * 8 + r];
                    ffma2(acc[2*r],     xx, wp.x);
                    ffma2(acc[2*r + 1], xx, wp.y);
                }
            }
        }
    }
    if (jv) {
        float4* o4 = (float4*)(out + (size_t)j * 32);
        const float4* s4 = (EPI == 1) ? (const float4*)(skip + (size_t)j * 32) : nullptr;
#pragma unroll
        for (int r = 0; r < 8; ++r) {
            F2U a0, a1; a0.u = acc[2*r]; a1.u = acc[2*r+1];
            float4 v = make_float4(a0.f.x, a0.f.y, a1.f.x, a1.f.y);
            if (EPI == 0) {
                v.x = fmaxf(v.x, 0.f); v.y = fmaxf(v.y, 0.f);
                v.z = fmaxf(v.z, 0.f); v.w = fmaxf(v.w, 0.f);
            }
            if (EPI == 1) {
                float4 sv = __ldg(s4 + r);
                v.x += sv.x; v.y += sv.y; v.z += sv.z; v.w += sv.w;
            }
            o4[r] = v;
        }
    }
}

// ---------------- host orchestration ----------------
extern "C" void kernel_launch(void* const* d_in, const int* in_sizes, int n_in,
                              void* d_out, int out_size) {
    const float* in_feats = (const float*)d_in[0];
    const float* W_first  = (const float*)d_in[1];
    const float* b_first  = (const float*)d_in[2];
    const float* W_pre    = (const float*)d_in[3];
    const float* b_pre    = (const float*)d_in[4];
    const float* W_down   = (const float*)d_in[5];
    const float* b_down   = (const float*)d_in[6];
    const float* W_r0     = (const float*)d_in[7];
    const float* b_r0     = (const float*)d_in[8];
    const float* W_r1     = (const float*)d_in[9];
    const float* b_r1     = (const float*)d_in[10];
    const float* W_fin    = (const float*)d_in[11];
    const float* b_fin    = (const float*)d_in[12];
    const int* km0_in  = (const int*)d_in[13];
    const int* km0_out = (const int*)d_in[14];
    const int* kmd_in  = (const int*)d_in[15];
    const int* kmd_out = (const int*)d_in[16];
    const int* km1_in  = (const int*)d_in[17];
    const int* km1_out = (const int*)d_in[18];

    const int n0 = in_sizes[0];
    const int P0 = in_sizes[13] / 27;
    const int Pd = in_sizes[15] / 8;
    const int P1 = in_sizes[17] / 27;
    const int n1 = (out_size - n0 * 16) / 32;

    float* out_fin    = (float*)d_out;
    float* out_cached = (float*)d_out + (size_t)n1 * 32;

    float *x0, *x1, *x2, *r0, *r1;
    int *gi0, *gid, *gi1;
    cudaGetSymbolAddress((void**)&x0, g_x0);
    cudaGetSymbolAddress((void**)&x1, g_x1);
    cudaGetSymbolAddress((void**)&x2, g_x2);
    cudaGetSymbolAddress((void**)&r0, g_r0);
    cudaGetSymbolAddress((void**)&r1, g_r1);
    cudaGetSymbolAddress((void**)&gi0, g_gi0);
    cudaGetSymbolAddress((void**)&gid, g_gid);
    cudaGetSymbolAddress((void**)&gi1, g_gi1);

    const int SMEM32 = 27 * 256 * sizeof(float4);  // 110592 B
    static bool attr_done = false;
    if (!attr_done) {
        cudaFuncSetAttribute(conv32_32<0>, cudaFuncAttributeMaxDynamicSharedMemorySize, SMEM32);
        cudaFuncSetAttribute(conv32_32<1>, cudaFuncAttributeMaxDynamicSharedMemorySize, SMEM32);
        cudaFuncSetAttribute(conv32_32<2>, cudaFuncAttributeMaxDynamicSharedMemorySize, SMEM32);
        attr_done = true;
    }

    auto ceil_div = [](int a, int b) { return (a + b - 1) / b; };
    const int T = 256;

    // ---- build inverse maps ----
    cudaMemsetAsync(gi0, 0xFF, (size_t)27 * n0 * sizeof(int), 0);
    cudaMemsetAsync(gid, 0xFF, (size_t)8 * n1 * sizeof(int), 0);
    cudaMemsetAsync(gi1, 0xFF, (size_t)27 * n1 * sizeof(int), 0);
    {
        dim3 g0(ceil_div(P0, T), 27);
        build_gi<<<g0, T>>>(km0_in, km0_out, gi0, P0, n0);
        dim3 gd(ceil_div(Pd, T), 8);
        build_gi<<<gd, T>>>(kmd_in, kmd_out, gid, Pd, n1);
        dim3 g1(ceil_div(P1, T), 27);
        build_gi<<<g1, T>>>(km1_in, km1_out, gi1, P1, n1);
    }

    conv1_16<<<ceil_div(n0, T), T>>>(in_feats, W_first, gi0, b_first, x0, out_cached, n0);
    conv16_16<<<ceil_div(n0, T), T>>>(x0, W_pre, gi0, b_pre, x1, n0);
    conv16_32<<<ceil_div(n1, T), T>>>(x1, W_down, gid, b_down, x2, n1);
    conv32_32<0><<<ceil_div(n1, T), T, SMEM32>>>(x2, W_r0, gi1, b_r0, nullptr, r0, n1);
    conv32_32<1><<<ceil_div(n1, T), T, SMEM32>>>(r0, W_r1, gi1, b_r1, x2, r1, n1);
    conv32_32<2><<<ceil_div(n1, T), T, SMEM32>>>(r1, W_fin, gi1, b_fin, nullptr, out_fin, n1);
}